// round 2
// baseline (speedup 1.0000x reference)
#include <cuda_runtime.h>
#include <math.h>

// Problem constants (B=4, S=1024, H=2048, I=2048, E=8, top_k=2)
#define TT   4096      // tokens
#define HH   2048      // hidden
#define EE   8         // experts
#define II   2048      // intermediate
#define I2   4096      // 2*I
#define NASS (TT * 2)  // total assignments (top_k = 2)

// -------- scratch (device globals; no allocations allowed) --------
__device__ int   g_topk_idx[TT * 2];
__device__ float g_topk_w[TT * 2];
__device__ int   g_cnt[EE];
__device__ int   g_off[EE];
__device__ int   g_cur[EE];
__device__ int   g_rowtok[NASS];
__device__ float g_roww[NASS];
__device__ float g_act[(size_t)NASS * II];   // 8192 x 2048 f32 = 64 MB

// ------------------------------------------------------------------
__global__ void zero_counts_kernel() {
    if (threadIdx.x < EE) { g_cnt[threadIdx.x] = 0; g_cur[threadIdx.x] = 0; }
}

// One block (256 threads) per token: logits over 8 experts, softmax top-2.
__global__ void gate_kernel(const float* __restrict__ x,
                            const float* __restrict__ gw) {
    int t   = blockIdx.x;
    int tid = threadIdx.x;
    float acc[EE];
#pragma unroll
    for (int e = 0; e < EE; e++) acc[e] = 0.f;
    for (int h = tid; h < HH; h += 256) {
        float xv = x[(size_t)t * HH + h];
#pragma unroll
        for (int e = 0; e < EE; e++) acc[e] += xv * gw[e * HH + h];
    }
    __shared__ float red[EE][256];
#pragma unroll
    for (int e = 0; e < EE; e++) red[e][tid] = acc[e];
    __syncthreads();
    for (int s = 128; s > 0; s >>= 1) {
        if (tid < s) {
#pragma unroll
            for (int e = 0; e < EE; e++) red[e][tid] += red[e][tid + s];
        }
        __syncthreads();
    }
    if (tid == 0) {
        float lg[EE];
#pragma unroll
        for (int e = 0; e < EE; e++) lg[e] = red[e][0];
        int i1 = 0;
#pragma unroll
        for (int e = 1; e < EE; e++) if (lg[e] > lg[i1]) i1 = e;
        int i2 = -1;
#pragma unroll
        for (int e = 0; e < EE; e++)
            if (e != i1 && (i2 < 0 || lg[e] > lg[i2])) i2 = e;
        // normalized top-2 weights: p1/(p1+p2) = 1/(1+exp(l2-l1))
        float w1 = 1.f / (1.f + expf(lg[i2] - lg[i1]));
        float w2 = 1.f - w1;
        g_topk_idx[t * 2 + 0] = i1;
        g_topk_idx[t * 2 + 1] = i2;
        g_topk_w[t * 2 + 0]   = w1;
        g_topk_w[t * 2 + 1]   = w2;
        atomicAdd(&g_cnt[i1], 1);
        atomicAdd(&g_cnt[i2], 1);
    }
}

__global__ void scan_kernel() {
    if (threadIdx.x == 0) {
        int s = 0;
        for (int e = 0; e < EE; e++) { g_off[e] = s; s += g_cnt[e]; }
    }
}

__global__ void scatter_kernel() {
    int t = blockIdx.x * blockDim.x + threadIdx.x;
    if (t >= TT) return;
#pragma unroll
    for (int k = 0; k < 2; k++) {
        int e   = g_topk_idx[t * 2 + k];
        int pos = g_off[e] + atomicAdd(&g_cur[e], 1);
        g_rowtok[pos] = t;
        g_roww[pos]   = g_topk_w[t * 2 + k];
    }
}

// ------------------------------------------------------------------
// FC1 GEMM (gathered rows) + fused SwiGLU epilogue -> g_act
// C[m][f] = sum_k x[tok[m]][k] * fc1_w[e][f][k] + b1[e][f]
// tile: BM=64, BN=64, BK=16, 256 threads, 4x4 per thread
__global__ void fc1_kernel(const float* __restrict__ x,
                           const float* __restrict__ w1,
                           const float* __restrict__ b1) {
    int e   = blockIdx.z;
    int cnt = g_cnt[e];
    int m0  = blockIdx.y * 64;
    if (m0 >= cnt) return;
    int off = g_off[e];
    int n0  = blockIdx.x * 64;
    const float* wB = w1 + (size_t)e * I2 * HH;

    __shared__ float As[16][64];
    __shared__ float Bs[16][64];
    __shared__ int   s_tok[64];

    int tid = threadIdx.x;
    if (tid < 64) {
        int m = m0 + tid;
        s_tok[tid] = (m < cnt) ? g_rowtok[off + m] : g_rowtok[off];
    }
    __syncthreads();

    int tx = tid & 15, ty = tid >> 4;
    int lm = tid >> 2;            // 0..63
    int lk = (tid & 3) * 4;       // 0,4,8,12

    float c[4][4];
#pragma unroll
    for (int i = 0; i < 4; i++)
#pragma unroll
        for (int j = 0; j < 4; j++) c[i][j] = 0.f;

    const float* aptr = x  + (size_t)s_tok[lm] * HH + lk;
    const float* bptr = wB + (size_t)(n0 + lm) * HH + lk;

    for (int kk = 0; kk < HH; kk += 16) {
        float4 av = *(const float4*)(aptr + kk);
        float4 bv = *(const float4*)(bptr + kk);
        As[lk + 0][lm] = av.x; As[lk + 1][lm] = av.y;
        As[lk + 2][lm] = av.z; As[lk + 3][lm] = av.w;
        Bs[lk + 0][lm] = bv.x; Bs[lk + 1][lm] = bv.y;
        Bs[lk + 2][lm] = bv.z; Bs[lk + 3][lm] = bv.w;
        __syncthreads();
#pragma unroll
        for (int k = 0; k < 16; k++) {
            float4 a = *(const float4*)&As[k][ty * 4];
            float4 b = *(const float4*)&Bs[k][tx * 4];
            c[0][0] += a.x * b.x; c[0][1] += a.x * b.y; c[0][2] += a.x * b.z; c[0][3] += a.x * b.w;
            c[1][0] += a.y * b.x; c[1][1] += a.y * b.y; c[1][2] += a.y * b.z; c[1][3] += a.y * b.w;
            c[2][0] += a.z * b.x; c[2][1] += a.z * b.y; c[2][2] += a.z * b.z; c[2][3] += a.z * b.w;
            c[3][0] += a.w * b.x; c[3][1] += a.w * b.y; c[3][2] += a.w * b.z; c[3][3] += a.w * b.w;
        }
        __syncthreads();
    }

    // SwiGLU epilogue: f even -> gate, f odd -> linear; act col = f/2
#pragma unroll
    for (int i = 0; i < 4; i++) {
        int m = m0 + ty * 4 + i;
        if (m >= cnt) continue;
#pragma unroll
        for (int jp = 0; jp < 2; jp++) {
            int f0 = n0 + tx * 4 + jp * 2;              // even
            float g = c[i][jp * 2 + 0] + b1[e * I2 + f0];
            float l = c[i][jp * 2 + 1] + b1[e * I2 + f0 + 1];
            float sg = 1.f / (1.f + expf(-1.702f * g));
            float a  = g * sg * (l + 1.f);
            g_act[(size_t)(off + m) * II + (f0 >> 1)] = a;
        }
    }
}

// ------------------------------------------------------------------
// FC2 GEMM + bias + weighted combine (atomicAdd into out)
__global__ void fc2_kernel(const float* __restrict__ w2,
                           const float* __restrict__ b2,
                           float* __restrict__ out) {
    int e   = blockIdx.z;
    int cnt = g_cnt[e];
    int m0  = blockIdx.y * 64;
    if (m0 >= cnt) return;
    int off = g_off[e];
    int n0  = blockIdx.x * 64;
    const float* wB = w2 + (size_t)e * HH * II;

    __shared__ float As[16][64];
    __shared__ float Bs[16][64];

    int tid = threadIdx.x;
    int tx = tid & 15, ty = tid >> 4;
    int lm = tid >> 2;
    int lk = (tid & 3) * 4;

    float c[4][4];
#pragma unroll
    for (int i = 0; i < 4; i++)
#pragma unroll
        for (int j = 0; j < 4; j++) c[i][j] = 0.f;

    int mr = m0 + lm; if (mr >= cnt) mr = cnt - 1;   // clamp A row (stay in-bounds)
    const float* aptr = g_act + (size_t)(off + mr) * II + lk;
    const float* bptr = wB    + (size_t)(n0 + lm) * II + lk;

    for (int kk = 0; kk < II; kk += 16) {
        float4 av = *(const float4*)(aptr + kk);
        float4 bv = *(const float4*)(bptr + kk);
        As[lk + 0][lm] = av.x; As[lk + 1][lm] = av.y;
        As[lk + 2][lm] = av.z; As[lk + 3][lm] = av.w;
        Bs[lk + 0][lm] = bv.x; Bs[lk + 1][lm] = bv.y;
        Bs[lk + 2][lm] = bv.z; Bs[lk + 3][lm] = bv.w;
        __syncthreads();
#pragma unroll
        for (int k = 0; k < 16; k++) {
            float4 a = *(const float4*)&As[k][ty * 4];
            float4 b = *(const float4*)&Bs[k][tx * 4];
            c[0][0] += a.x * b.x; c[0][1] += a.x * b.y; c[0][2] += a.x * b.z; c[0][3] += a.x * b.w;
            c[1][0] += a.y * b.x; c[1][1] += a.y * b.y; c[1][2] += a.y * b.z; c[1][3] += a.y * b.w;
            c[2][0] += a.z * b.x; c[2][1] += a.z * b.y; c[2][2] += a.z * b.z; c[2][3] += a.z * b.w;
            c[3][0] += a.w * b.x; c[3][1] += a.w * b.y; c[3][2] += a.w * b.z; c[3][3] += a.w * b.w;
        }
        __syncthreads();
    }

#pragma unroll
    for (int i = 0; i < 4; i++) {
        int m = m0 + ty * 4 + i;
        if (m >= cnt) continue;
        int row = off + m;
        int tok = g_rowtok[row];
        float w = g_roww[row];
#pragma unroll
        for (int j = 0; j < 4; j++) {
            int hh  = n0 + tx * 4 + j;
            float y = c[i][j] + b2[e * HH + hh];
            atomicAdd(&out[(size_t)tok * HH + hh], w * y);
        }
    }
}

// ------------------------------------------------------------------
extern "C" void kernel_launch(void* const* d_in, const int* in_sizes, int n_in,
                              void* d_out, int out_size) {
    const float* x  = (const float*)d_in[0];  // hidden_states (B,S,H)
    const float* gw = (const float*)d_in[1];  // gate_w (E,H)
    const float* w1 = (const float*)d_in[2];  // fc1_w (E,2I,H)
    const float* b1 = (const float*)d_in[3];  // fc1_b (E,2I)
    const float* w2 = (const float*)d_in[4];  // fc2_w (E,H,I)
    const float* b2 = (const float*)d_in[5];  // fc2_b (E,H)
    float* out = (float*)d_out;

    cudaMemsetAsync(out, 0, (size_t)TT * HH * sizeof(float), 0);
    zero_counts_kernel<<<1, 32>>>();
    gate_kernel<<<TT, 256>>>(x, gw);
    scan_kernel<<<1, 32>>>();
    scatter_kernel<<<(TT + 255) / 256, 256>>>();
    fc1_kernel<<<dim3(I2 / 64, NASS / 64, EE), 256>>>(x, w1, b1);
    fc2_kernel<<<dim3(HH / 64, NASS / 64, EE), 256>>>(w2, b2, out);
}

// round 5
// speedup vs baseline: 2.0956x; 2.0956x over previous
#include <cuda_runtime.h>
#include <cuda_bf16.h>
#include <cstdint>
#include <math.h>

// Problem constants (B=4, S=1024, H=2048, I=2048, E=8, top_k=2)
#define TT   4096
#define HH   2048
#define EE   8
#define II   2048
#define I2   4096
#define NASS (TT * 2)
#define KDIM 2048
#define BM   128
#define BN   128
#define BK   32
#define NCHUNK (KDIM / BK)   // 64
#define STRD 40              // halves per smem tile row (32 + 8 pad -> conflict-free ldmatrix)

// ---------------- scratch ----------------
__device__ int   g_topk_idx[TT * 2];
__device__ float g_topk_w[TT * 2];
__device__ int   g_cnt[EE];
__device__ int   g_off[EE];
__device__ int   g_cur[EE];
__device__ int   g_rowtok[NASS];
__device__ float g_roww[NASS];
__device__ float g_act[(size_t)NASS * II];   // 64 MB

// ---------------- helpers ----------------
__device__ __forceinline__ uint32_t s2u(const void* p) {
    uint32_t a;
    asm("{ .reg .u64 t; cvta.to.shared.u64 t, %1; cvt.u32.u64 %0, t; }" : "=r"(a) : "l"(p));
    return a;
}
__device__ __forceinline__ void ldm_x4(uint32_t* r, uint32_t addr) {
    asm volatile("ldmatrix.sync.aligned.m8n8.x4.shared.b16 {%0,%1,%2,%3}, [%4];"
                 : "=r"(r[0]), "=r"(r[1]), "=r"(r[2]), "=r"(r[3]) : "r"(addr));
}
__device__ __forceinline__ void mma16816(float* d, const uint32_t* a, uint32_t b0, uint32_t b1) {
    asm volatile("mma.sync.aligned.m16n8k16.row.col.f32.bf16.bf16.f32 "
                 "{%0,%1,%2,%3}, {%4,%5,%6,%7}, {%8,%9}, {%0,%1,%2,%3};"
                 : "+f"(d[0]), "+f"(d[1]), "+f"(d[2]), "+f"(d[3])
                 : "r"(a[0]), "r"(a[1]), "r"(a[2]), "r"(a[3]), "r"(b0), "r"(b1));
}
// split one float4 into hi/lo bf16 and store 4 halves to each tile at &tile[row][col]
__device__ __forceinline__ void split_st(__nv_bfloat16* hi, __nv_bfloat16* lo, float4 v) {
    __nv_bfloat16 h0 = __float2bfloat16_rn(v.x), h1 = __float2bfloat16_rn(v.y);
    __nv_bfloat16 h2 = __float2bfloat16_rn(v.z), h3 = __float2bfloat16_rn(v.w);
    ((__nv_bfloat162*)hi)[0] = __halves2bfloat162(h0, h1);
    ((__nv_bfloat162*)hi)[1] = __halves2bfloat162(h2, h3);
    ((__nv_bfloat162*)lo)[0] = __floats2bfloat162_rn(v.x - __bfloat162float(h0),
                                                     v.y - __bfloat162float(h1));
    ((__nv_bfloat162*)lo)[1] = __floats2bfloat162_rn(v.z - __bfloat162float(h2),
                                                     v.w - __bfloat162float(h3));
}

// ---------------- routing ----------------
__global__ void zero_counts_kernel() {
    if (threadIdx.x < EE) { g_cnt[threadIdx.x] = 0; g_cur[threadIdx.x] = 0; }
}

__global__ void gate_kernel(const float* __restrict__ x, const float* __restrict__ gw) {
    int t = blockIdx.x, tid = threadIdx.x;
    float acc[EE];
#pragma unroll
    for (int e = 0; e < EE; e++) acc[e] = 0.f;
    for (int h = tid; h < HH; h += 256) {
        float xv = x[(size_t)t * HH + h];
#pragma unroll
        for (int e = 0; e < EE; e++) acc[e] += xv * gw[e * HH + h];
    }
    __shared__ float red[EE][256];
#pragma unroll
    for (int e = 0; e < EE; e++) red[e][tid] = acc[e];
    __syncthreads();
    for (int s = 128; s > 0; s >>= 1) {
        if (tid < s) {
#pragma unroll
            for (int e = 0; e < EE; e++) red[e][tid] += red[e][tid + s];
        }
        __syncthreads();
    }
    if (tid == 0) {
        float lg[EE];
#pragma unroll
        for (int e = 0; e < EE; e++) lg[e] = red[e][0];
        int i1 = 0;
#pragma unroll
        for (int e = 1; e < EE; e++) if (lg[e] > lg[i1]) i1 = e;
        int i2 = -1;
#pragma unroll
        for (int e = 0; e < EE; e++)
            if (e != i1 && (i2 < 0 || lg[e] > lg[i2])) i2 = e;
        float w1 = 1.f / (1.f + expf(lg[i2] - lg[i1]));
        g_topk_idx[t * 2 + 0] = i1; g_topk_idx[t * 2 + 1] = i2;
        g_topk_w[t * 2 + 0] = w1;   g_topk_w[t * 2 + 1] = 1.f - w1;
        atomicAdd(&g_cnt[i1], 1);   atomicAdd(&g_cnt[i2], 1);
    }
}

__global__ void scan_kernel() {
    if (threadIdx.x == 0) {
        int s = 0;
        for (int e = 0; e < EE; e++) { g_off[e] = s; s += g_cnt[e]; }
    }
}

__global__ void scatter_kernel() {
    int t = blockIdx.x * blockDim.x + threadIdx.x;
    if (t >= TT) return;
#pragma unroll
    for (int k = 0; k < 2; k++) {
        int e = g_topk_idx[t * 2 + k];
        int pos = g_off[e] + atomicAdd(&g_cur[e], 1);
        g_rowtok[pos] = t;
        g_roww[pos]   = g_topk_w[t * 2 + k];
    }
}

// ---------------- split-bf16 HMMA GEMM ----------------
// IS_FC1=1: D = gather(x) @ w1^T, epilogue bias+SwiGLU -> g_act
// IS_FC1=0: D = g_act @ w2^T,     epilogue bias + weighted atomic combine -> out
template <int IS_FC1>
__global__ void __launch_bounds__(256) moe_gemm(
    const float* __restrict__ X, const float* __restrict__ W,
    const float* __restrict__ bias, float* __restrict__ outp)
{
    __shared__ __nv_bfloat16 sAh[BM][STRD], sAl[BM][STRD];
    __shared__ __nv_bfloat16 sBh[BN][STRD], sBl[BN][STRD];
    __shared__ int s_row[BM];

    int e   = blockIdx.z;
    int cnt = g_cnt[e];
    int m0  = blockIdx.y * BM;
    if (m0 >= cnt) return;
    int off = g_off[e];
    int n0  = blockIdx.x * BN;
    const int NTOT = IS_FC1 ? I2 : HH;
    const float* WB = W + (size_t)e * NTOT * KDIM;
    int tid = threadIdx.x;

    if (tid < BM) {
        int m = m0 + tid;
        if (IS_FC1) s_row[tid] = (m < cnt) ? g_rowtok[off + m] : g_rowtok[off];
        else        s_row[tid] = off + ((m < cnt) ? m : cnt - 1);
    }
    __syncthreads();

    int rA = tid >> 1;
    int c0 = (tid & 1) * 16;
    const float* Asrc = IS_FC1 ? X : g_act;
    const float* ap = Asrc + (size_t)s_row[rA] * KDIM + c0;
    const float* bp = WB + (size_t)(n0 + rA) * KDIM + c0;

    int lane = tid & 31, wid = tid >> 5;
    int wm = (wid & 3) * 32;        // warp row base
    int wn = (wid >> 2) * 64;       // warp col base
    int lrow = lane & 15;
    int lcol8 = (lane >> 4) * 8;

    float acc[2][8][4];
#pragma unroll
    for (int i = 0; i < 2; i++)
#pragma unroll
        for (int j = 0; j < 8; j++)
#pragma unroll
            for (int k = 0; k < 4; k++) acc[i][j][k] = 0.f;

    float4 ra[4], rb[4];
    // prologue: load + store chunk 0
#pragma unroll
    for (int i = 0; i < 4; i++) { ra[i] = *(const float4*)(ap + i * 4); rb[i] = *(const float4*)(bp + i * 4); }
#pragma unroll
    for (int i = 0; i < 4; i++) {
        split_st(&sAh[rA][c0 + i * 4], &sAl[rA][c0 + i * 4], ra[i]);
        split_st(&sBh[rA][c0 + i * 4], &sBl[rA][c0 + i * 4], rb[i]);
    }
    __syncthreads();

    for (int c = 0; c < NCHUNK; c++) {
        if (c + 1 < NCHUNK) {
            const float* a2 = ap + (c + 1) * BK;
            const float* b2 = bp + (c + 1) * BK;
#pragma unroll
            for (int i = 0; i < 4; i++) { ra[i] = *(const float4*)(a2 + i * 4); rb[i] = *(const float4*)(b2 + i * 4); }
        }
#pragma unroll
        for (int ks = 0; ks < 2; ks++) {
            uint32_t ah[2][4], al[2][4];
#pragma unroll
            for (int mi = 0; mi < 2; mi++) {
                int row = wm + mi * 16 + lrow;
                int col = ks * 16 + lcol8;
                ldm_x4(ah[mi], s2u(&sAh[row][col]));
                ldm_x4(al[mi], s2u(&sAl[row][col]));
            }
#pragma unroll
            for (int bq = 0; bq < 4; bq++) {
                uint32_t bh[4], bl[4];
                int row = wn + bq * 16 + lrow;
                int col = ks * 16 + lcol8;
                ldm_x4(bh, s2u(&sBh[row][col]));
                ldm_x4(bl, s2u(&sBl[row][col]));
#pragma unroll
                for (int mi = 0; mi < 2; mi++) {
                    mma16816(acc[mi][bq * 2 + 0], ah[mi], bh[0], bh[2]);
                    mma16816(acc[mi][bq * 2 + 0], ah[mi], bl[0], bl[2]);
                    mma16816(acc[mi][bq * 2 + 0], al[mi], bh[0], bh[2]);
                    mma16816(acc[mi][bq * 2 + 1], ah[mi], bh[1], bh[3]);
                    mma16816(acc[mi][bq * 2 + 1], ah[mi], bl[1], bl[3]);
                    mma16816(acc[mi][bq * 2 + 1], al[mi], bh[1], bh[3]);
                }
            }
        }
        __syncthreads();
        if (c + 1 < NCHUNK) {
#pragma unroll
            for (int i = 0; i < 4; i++) {
                split_st(&sAh[rA][c0 + i * 4], &sAl[rA][c0 + i * 4], ra[i]);
                split_st(&sBh[rA][c0 + i * 4], &sBl[rA][c0 + i * 4], rb[i]);
            }
            __syncthreads();
        }
    }

    // -------- epilogue --------
#pragma unroll
    for (int mi = 0; mi < 2; mi++) {
#pragma unroll
        for (int h = 0; h < 2; h++) {
            int m = m0 + wm + mi * 16 + (lane >> 2) + h * 8;
            if (m >= cnt) continue;
            if (IS_FC1) {
                size_t rowo = (size_t)(off + m) * II;
#pragma unroll
                for (int nb = 0; nb < 8; nb++) {
                    int f = n0 + wn + nb * 8 + (lane & 3) * 2;    // even column
                    float g = acc[mi][nb][h * 2 + 0] + bias[(size_t)e * NTOT + f];
                    float l = acc[mi][nb][h * 2 + 1] + bias[(size_t)e * NTOT + f + 1];
                    float sg = 1.f / (1.f + expf(-1.702f * g));
                    g_act[rowo + (f >> 1)] = g * sg * (l + 1.f);
                }
            } else {
                int row = off + m;
                int tok = g_rowtok[row];
                float w = g_roww[row];
                size_t o = (size_t)tok * HH;
#pragma unroll
                for (int nb = 0; nb < 8; nb++) {
                    int f = n0 + wn + nb * 8 + (lane & 3) * 2;
                    float y0 = acc[mi][nb][h * 2 + 0] + bias[(size_t)e * NTOT + f];
                    float y1 = acc[mi][nb][h * 2 + 1] + bias[(size_t)e * NTOT + f + 1];
                    atomicAdd(&outp[o + f],     w * y0);
                    atomicAdd(&outp[o + f + 1], w * y1);
                }
            }
        }
    }
}

// ---------------- launch ----------------
extern "C" void kernel_launch(void* const* d_in, const int* in_sizes, int n_in,
                              void* d_out, int out_size) {
    const float* x  = (const float*)d_in[0];
    const float* gw = (const float*)d_in[1];
    const float* w1 = (const float*)d_in[2];
    const float* b1 = (const float*)d_in[3];
    const float* w2 = (const float*)d_in[4];
    const float* b2 = (const float*)d_in[5];
    float* out = (float*)d_out;

    cudaMemsetAsync(out, 0, (size_t)TT * HH * sizeof(float), 0);
    zero_counts_kernel<<<1, 32>>>();
    gate_kernel<<<TT, 256>>>(x, gw);
    scan_kernel<<<1, 32>>>();
    scatter_kernel<<<(TT + 255) / 256, 256>>>();
    moe_gemm<1><<<dim3(I2 / BN, NASS / BM, EE), 256>>>(x, w1, b1, nullptr);
    moe_gemm<0><<<dim3(HH / BN, NASS / BM, EE), 256>>>(x, w2, b2, out);
}